// round 4
// baseline (speedup 1.0000x reference)
#include <cuda_runtime.h>
#include <math.h>

#define Bn 32
#define Tn 2048
#define Dn 256
#define Hn 256
#define An 128
#define Cn 4367
#define CP 4368
#define NSTEPS 22
#define G3H 768

// ---------------- scratch (static device globals; no allocation) ----------------
__device__ float g_xWT[(size_t)Bn * An * Tn];   // [b][a][t]  ~33.5 MB
__device__ float g_h[Bn * Hn];
__device__ float g_q[Bn * An];
__device__ float g_ctx[Bn * Dn];                // unnormalized ctx accumulator
__device__ float g_sumw[Bn];
__device__ float g_gi[Bn * G3H];
__device__ float g_gh[Bn * G3H];
__device__ float g_WihT[Dn * G3H];              // [k][j]
__device__ float g_WhhT[Hn * G3H];              // [k][j]
__device__ float g_WclsT[Hn * CP];              // [k][c] padded to 4368

// ---------------- init: transposes + zero state ----------------
__global__ void k_init(const float* __restrict__ W_ih,
                       const float* __restrict__ W_hh,
                       const float* __restrict__ W_cls) {
    int idx = blockIdx.x * blockDim.x + threadIdx.x;
    int stride = gridDim.x * blockDim.x;
    for (int i = idx; i < G3H * Dn; i += stride) {
        int j = i / Dn, k = i % Dn;
        g_WihT[k * G3H + j] = W_ih[i];
        g_WhhT[k * G3H + j] = W_hh[i];
    }
    for (int i = idx; i < Cn * Hn; i += stride) {
        int c = i / Hn, k = i % Hn;
        g_WclsT[k * CP + c] = W_cls[i];
    }
    for (int i = idx; i < Bn * Hn; i += stride) { g_h[i] = 0.f; g_ctx[i] = 0.f; }
    for (int i = idx; i < Bn * An; i += stride) g_q[i] = 0.f;
    if (idx < Bn) g_sumw[idx] = 0.f;
}

// ---------------- xW GEMM: [65536,256] @ [256,128] -> transposed [b][a][t] ----------------
__global__ __launch_bounds__(256) void k_xw(const float* __restrict__ x,
                                            const float* __restrict__ Wx) {
    __shared__ float As[128][9];   // [t][k] padded
    __shared__ float Bs[8][128];   // [k][a]
    int rb = blockIdx.x;           // 512 blocks, 128 rows each (t-tiles never cross b)
    int row0 = rb * 128;
    int b = row0 / Tn;
    int t0 = row0 % Tn;
    int tid = threadIdx.x;
    int tt = tid / 16;             // t group (8 rows)
    int ta = tid % 16;             // a group (8 cols)

    float acc[8][8];
#pragma unroll
    for (int i = 0; i < 8; i++)
#pragma unroll
        for (int j = 0; j < 8; j++) acc[i][j] = 0.f;

    int lr = tid >> 1;             // As load: row
    int lp = tid & 1;              // half (2 float4 per row of 8 k)
    int lk = tid >> 5;             // Bs load: k row
    int la = tid & 31;             // float4 col

    for (int k0 = 0; k0 < 256; k0 += 8) {
        float4 xa = *(const float4*)(x + (size_t)(row0 + lr) * Dn + k0 + lp * 4);
        As[lr][lp * 4 + 0] = xa.x; As[lr][lp * 4 + 1] = xa.y;
        As[lr][lp * 4 + 2] = xa.z; As[lr][lp * 4 + 3] = xa.w;
        float4 wv = *(const float4*)(Wx + (size_t)(k0 + lk) * An + la * 4);
        *(float4*)(&Bs[lk][la * 4]) = wv;
        __syncthreads();
#pragma unroll
        for (int kk = 0; kk < 8; kk++) {
            float af[8], bf[8];
#pragma unroll
            for (int i = 0; i < 8; i++) af[i] = As[tt * 8 + i][kk];
#pragma unroll
            for (int j = 0; j < 8; j++) bf[j] = Bs[kk][ta * 8 + j];
#pragma unroll
            for (int i = 0; i < 8; i++)
#pragma unroll
                for (int j = 0; j < 8; j++) acc[i][j] += af[i] * bf[j];
        }
        __syncthreads();
    }
#pragma unroll
    for (int j = 0; j < 8; j++) {
        int a = ta * 8 + j;
        float* dst = g_xWT + ((size_t)b * An + a) * Tn + t0 + tt * 8;
        float4 v0 = make_float4(acc[0][j], acc[1][j], acc[2][j], acc[3][j]);
        float4 v1 = make_float4(acc[4][j], acc[5][j], acc[6][j], acc[7][j]);
        *(float4*)dst = v0;
        *(float4*)(dst + 4) = v1;
    }
}

// ---------------- fused: attention step s  +  classifier for step s-1 ----------------
// attn blocks: bid < n_attn  (512 = 16 t-chunks x 32 b), 128 threads, t-chunk 128
// cls  blocks: bid >= n_attn (140 = 35 c-tiles x 4 b-groups), 128 threads
__global__ __launch_bounds__(128) void k_attn_cls(const float* __restrict__ x,
                                                  const float* __restrict__ v,
                                                  const float* __restrict__ b_cls,
                                                  float* __restrict__ out,
                                                  int cls_step, int n_attn) {
    int bid = blockIdx.x;
    int tid = threadIdx.x;

    if (bid < n_attn) {
        // ---- attention ----
        int chunk = bid & 15;
        int b = bid >> 4;
        int t0 = chunk * 128;

        __shared__ float q_s[An];
        __shared__ float v_s[An];
        __shared__ float w_s[128];
        __shared__ float red[4];

        q_s[tid] = g_q[b * An + tid];
        v_s[tid] = v[tid];
        __syncthreads();

        // phase A: e over A=128 (coalesced across t)
        const float* xw = g_xWT + (size_t)b * An * Tn + (t0 + tid);
        float e0 = 0.f, e1 = 0.f, e2 = 0.f, e3 = 0.f;
#pragma unroll 4
        for (int a = 0; a < An; a += 4) {
            float z0 = xw[(size_t)(a + 0) * Tn] + q_s[a + 0];
            float z1 = xw[(size_t)(a + 1) * Tn] + q_s[a + 1];
            float z2 = xw[(size_t)(a + 2) * Tn] + q_s[a + 2];
            float z3 = xw[(size_t)(a + 3) * Tn] + q_s[a + 3];
            float th0, th1, th2, th3;
            asm("tanh.approx.f32 %0, %1;" : "=f"(th0) : "f"(z0));
            asm("tanh.approx.f32 %0, %1;" : "=f"(th1) : "f"(z1));
            asm("tanh.approx.f32 %0, %1;" : "=f"(th2) : "f"(z2));
            asm("tanh.approx.f32 %0, %1;" : "=f"(th3) : "f"(z3));
            e0 += th0 * v_s[a + 0];
            e1 += th1 * v_s[a + 1];
            e2 += th2 * v_s[a + 2];
            e3 += th3 * v_s[a + 3];
        }
        // |e| <= sum|v| ~ 5 -> exp stable without max subtraction
        float w = __expf((e0 + e1) + (e2 + e3));
        w_s[tid] = w;

        float s = w;
#pragma unroll
        for (int o = 16; o > 0; o >>= 1) s += __shfl_xor_sync(0xffffffffu, s, o);
        if ((tid & 31) == 0) red[tid >> 5] = s;
        __syncthreads();
        if (tid == 0) atomicAdd(&g_sumw[b], (red[0] + red[1]) + (red[2] + red[3]));

        // phase B: partial ctx; 128 threads cover 256 d via float2
        const float* xp = x + ((size_t)b * Tn + t0) * Dn + tid * 2;
        float ax = 0.f, ay = 0.f, bx = 0.f, by = 0.f;
#pragma unroll 2
        for (int t = 0; t < 128; t += 2) {
            float2 x0 = *(const float2*)(xp + (size_t)(t + 0) * Dn);
            float2 x1 = *(const float2*)(xp + (size_t)(t + 1) * Dn);
            ax += w_s[t + 0] * x0.x; ay += w_s[t + 0] * x0.y;
            bx += w_s[t + 1] * x1.x; by += w_s[t + 1] * x1.y;
        }
        atomicAdd(&g_ctx[b * Dn + tid * 2 + 0], ax + bx);
        atomicAdd(&g_ctx[b * Dn + tid * 2 + 1], ay + by);
    } else {
        // ---- classifier for step cls_step (h already holds that step's state) ----
        if (cls_step < 0) return;
        int cid = bid - n_attn;
        int ctile = cid % 35;
        int bg = cid / 35;
        int c = ctile * 128 + tid;
        int b0 = bg * 8;

        __shared__ float hs[8 * 256];
        for (int i = tid; i < 8 * 256; i += 128) hs[i] = g_h[b0 * Hn + i];
        __syncthreads();

        if (c < Cn) {
            float acc[8];
#pragma unroll
            for (int bb = 0; bb < 8; bb++) acc[bb] = 0.f;
#pragma unroll 4
            for (int k = 0; k < 256; k++) {
                float wv = g_WclsT[(size_t)k * CP + c];
#pragma unroll
                for (int bb = 0; bb < 8; bb++) acc[bb] += hs[bb * 256 + k] * wv;
            }
            float bias = b_cls[c];
#pragma unroll
            for (int bb = 0; bb < 8; bb++)
                out[((size_t)(b0 + bb) * NSTEPS + cls_step) * Cn + c] = acc[bb] + bias;
        }
    }
}

// ---------------- GRU gate GEMMs, j-major: block = 128 j x 4 b ----------------
// grid (12 j-tiles, 8 b-groups); j-tiles 0..5 -> gi, 6..11 -> gh (uniform per block)
__global__ __launch_bounds__(128) void k_gates2(const float* __restrict__ b_ih,
                                                const float* __restrict__ b_hh) {
    int jt = blockIdx.x;
    int bg = blockIdx.y;
    int tid = threadIdx.x;
    int jg = jt * 128 + tid;           // 0..1535
    bool is_gi = (jt < 6);
    int jj = is_gi ? jg : jg - 768;

    __shared__ float src[4][256];      // broadcast reads -> no conflicts
    if (is_gi) {
        for (int i = tid; i < 4 * 256; i += 128) {
            int bb = i >> 8, k = i & 255;
            int b = bg * 4 + bb;
            src[bb][k] = g_ctx[b * Dn + k] * (1.f / g_sumw[b]);
        }
    } else {
        for (int i = tid; i < 4 * 256; i += 128) {
            int bb = i >> 8, k = i & 255;
            src[bb][k] = g_h[(bg * 4 + bb) * Hn + k];
        }
    }
    __syncthreads();

    const float* W = is_gi ? g_WihT : g_WhhT;
    float a0 = 0.f, a1 = 0.f, a2 = 0.f, a3 = 0.f;
#pragma unroll 8
    for (int k = 0; k < 256; k++) {
        float w = W[(size_t)k * G3H + jj];
        a0 += src[0][k] * w;
        a1 += src[1][k] * w;
        a2 += src[2][k] * w;
        a3 += src[3][k] * w;
    }
    float bv = is_gi ? b_ih[jj] : b_hh[jj];
    float* dst = is_gi ? g_gi : g_gh;
    dst[(bg * 4 + 0) * G3H + jj] = a0 + bv;
    dst[(bg * 4 + 1) * G3H + jj] = a1 + bv;
    dst[(bg * 4 + 2) * G3H + jj] = a2 + bv;
    dst[(bg * 4 + 3) * G3H + jj] = a3 + bv;
}

// ---------------- GRU combine + h update + q = h@Wh + zero scratch ----------------
__global__ __launch_bounds__(256) void k_update(const float* __restrict__ Wh) {
    int b = blockIdx.x;
    int tid = threadIdx.x;     // 256 = H
    __shared__ float hs[256];

    float i_r = g_gi[b * G3H + tid];
    float i_z = g_gi[b * G3H + 256 + tid];
    float i_n = g_gi[b * G3H + 512 + tid];
    float h_r = g_gh[b * G3H + tid];
    float h_z = g_gh[b * G3H + 256 + tid];
    float h_n = g_gh[b * G3H + 512 + tid];
    float hprev = g_h[b * Hn + tid];

    float r = 1.f / (1.f + expf(-(i_r + h_r)));
    float z = 1.f / (1.f + expf(-(i_z + h_z)));
    float n = tanhf(i_n + r * h_n);
    float hn = (1.f - z) * n + z * hprev;

    g_h[b * Hn + tid] = hn;
    hs[tid] = hn;
    g_ctx[b * Dn + tid] = 0.f;            // reset for next step
    if (tid == 0) g_sumw[b] = 0.f;
    __syncthreads();

    if (tid < An) {                        // q[a] = sum_k hs[k] * Wh[k][a]
        float acc0 = 0.f, acc1 = 0.f;
#pragma unroll 8
        for (int k = 0; k < 256; k += 2) {
            acc0 += hs[k] * Wh[(size_t)k * An + tid];
            acc1 += hs[k + 1] * Wh[(size_t)(k + 1) * An + tid];
        }
        g_q[b * An + tid] = acc0 + acc1;
    }
}

// ---------------- launch ----------------
extern "C" void kernel_launch(void* const* d_in, const int* in_sizes, int n_in,
                              void* d_out, int out_size) {
    const float* x     = (const float*)d_in[0];
    const float* Wx    = (const float*)d_in[1];
    const float* Wh    = (const float*)d_in[2];
    const float* v     = (const float*)d_in[3];
    const float* W_ih  = (const float*)d_in[4];
    const float* W_hh  = (const float*)d_in[5];
    const float* b_ih  = (const float*)d_in[6];
    const float* b_hh  = (const float*)d_in[7];
    const float* W_cls = (const float*)d_in[8];
    const float* b_cls = (const float*)d_in[9];
    float* out = (float*)d_out;

    k_init<<<1024, 256>>>(W_ih, W_hh, W_cls);
    k_xw<<<512, 256>>>(x, Wx);

    const int N_ATTN = 512;   // 16 t-chunks x 32 b
    const int N_CLS  = 140;   // 35 c-tiles x 4 b-groups

    for (int s = 0; s < NSTEPS; s++) {
        // attention for step s, classifier for step s-1 (independent work, one grid)
        k_attn_cls<<<N_ATTN + N_CLS, 128>>>(x, v, b_cls, out, s - 1, N_ATTN);
        k_gates2<<<dim3(12, 8), 128>>>(b_ih, b_hh);
        k_update<<<32, 256>>>(Wh);
    }
    // classifier for the final step
    k_attn_cls<<<N_CLS, 128>>>(x, v, b_cls, out, NSTEPS - 1, 0);

    (void)in_sizes; (void)n_in; (void)out_size;
}

// round 7
// speedup vs baseline: 1.3773x; 1.3773x over previous
#include <cuda_runtime.h>
#include <math.h>

#define Bn 32
#define Tn 2048
#define Dn 256
#define Hn 256
#define An 128
#define Cn 4367
#define CP 4368
#define NSTEPS 22
#define G3H 768

// ---------------- scratch (static device globals; no allocation) ----------------
__device__ float g_xWT[(size_t)Bn * An * Tn];   // [b][a][t]  ~33.5 MB
__device__ float g_h[Bn * Hn];
__device__ float g_q[Bn * An];
__device__ float g_ctx[Bn * Dn];                // unnormalized ctx accumulator
__device__ float g_sumw[Bn];
__device__ float g_gi[Bn * G3H];                // seeded with b_ih, atomically accumulated
__device__ float g_gh[Bn * G3H];                // seeded with b_hh, atomically accumulated
__device__ float g_WihT[Dn * G3H];              // [k][j]
__device__ float g_WhhT[Hn * G3H];              // [k][j]
__device__ float g_WclsT[Hn * CP];              // [k][c] padded to 4368

// ---------------- init: transposes + zero state + bias-seed gates ----------------
__global__ void k_init(const float* __restrict__ W_ih,
                       const float* __restrict__ W_hh,
                       const float* __restrict__ W_cls,
                       const float* __restrict__ b_ih,
                       const float* __restrict__ b_hh) {
    int idx = blockIdx.x * blockDim.x + threadIdx.x;
    int stride = gridDim.x * blockDim.x;
    for (int i = idx; i < G3H * Dn; i += stride) {
        int j = i / Dn, k = i % Dn;
        g_WihT[k * G3H + j] = W_ih[i];
        g_WhhT[k * G3H + j] = W_hh[i];
    }
    for (int i = idx; i < Cn * Hn; i += stride) {
        int c = i / Hn, k = i % Hn;
        g_WclsT[k * CP + c] = W_cls[i];
    }
    for (int i = idx; i < Bn * Hn; i += stride) { g_h[i] = 0.f; g_ctx[i] = 0.f; }
    for (int i = idx; i < Bn * An; i += stride) g_q[i] = 0.f;
    for (int i = idx; i < Bn * G3H; i += stride) {
        g_gi[i] = b_ih[i % G3H];
        g_gh[i] = b_hh[i % G3H];
    }
    if (idx < Bn) g_sumw[idx] = 0.f;
}

// ---------------- xW GEMM: [65536,256] @ [256,128] -> transposed [b][a][t] ----------------
__global__ __launch_bounds__(256) void k_xw(const float* __restrict__ x,
                                            const float* __restrict__ Wx) {
    __shared__ float As[128][17];  // [t][k] padded (17 -> conflict-free column reads)
    __shared__ float Bs[16][128];  // [k][a]
    int rb = blockIdx.x;           // 512 blocks, 128 rows each (t-tiles never cross b)
    int row0 = rb * 128;
    int b = row0 / Tn;
    int t0 = row0 % Tn;
    int tid = threadIdx.x;
    int tt = tid / 16;             // t group (8 rows)
    int ta = tid % 16;             // a group (8 cols)

    float acc[8][8];
#pragma unroll
    for (int i = 0; i < 8; i++)
#pragma unroll
        for (int j = 0; j < 8; j++) acc[i][j] = 0.f;

    int lr = tid >> 1;             // As load: row
    int lp = tid & 1;              // which 8-float half of the 16-k chunk
    int lk = tid >> 5;             // Bs load: k row (0..7; also lk+8)
    int la = tid & 31;             // float4 col

    for (int k0 = 0; k0 < 256; k0 += 16) {
        // global float4 loads; SCALAR smem stores (As rows are 68B stride, not 16B aligned)
        const float* xs = x + (size_t)(row0 + lr) * Dn + k0 + lp * 8;
        float4 xa0 = *(const float4*)(xs);
        float4 xa1 = *(const float4*)(xs + 4);
        As[lr][lp * 8 + 0] = xa0.x; As[lr][lp * 8 + 1] = xa0.y;
        As[lr][lp * 8 + 2] = xa0.z; As[lr][lp * 8 + 3] = xa0.w;
        As[lr][lp * 8 + 4] = xa1.x; As[lr][lp * 8 + 5] = xa1.y;
        As[lr][lp * 8 + 6] = xa1.z; As[lr][lp * 8 + 7] = xa1.w;
        float4 w0 = *(const float4*)(Wx + (size_t)(k0 + lk) * An + la * 4);
        float4 w1 = *(const float4*)(Wx + (size_t)(k0 + lk + 8) * An + la * 4);
        *(float4*)(&Bs[lk][la * 4]) = w0;      // Bs rows = 512B stride, 16B aligned
        *(float4*)(&Bs[lk + 8][la * 4]) = w1;
        __syncthreads();
#pragma unroll
        for (int kk = 0; kk < 16; kk++) {
            float af[8], bf[8];
#pragma unroll
            for (int i = 0; i < 8; i++) af[i] = As[tt * 8 + i][kk];
#pragma unroll
            for (int j = 0; j < 8; j++) bf[j] = Bs[kk][ta * 8 + j];
#pragma unroll
            for (int i = 0; i < 8; i++)
#pragma unroll
                for (int j = 0; j < 8; j++) acc[i][j] += af[i] * bf[j];
        }
        __syncthreads();
    }
#pragma unroll
    for (int j = 0; j < 8; j++) {
        int a = ta * 8 + j;
        float* dst = g_xWT + ((size_t)b * An + a) * Tn + t0 + tt * 8;
        float4 v0 = make_float4(acc[0][j], acc[1][j], acc[2][j], acc[3][j]);
        float4 v1 = make_float4(acc[4][j], acc[5][j], acc[6][j], acc[7][j]);
        *(float4*)dst = v0;
        *(float4*)(dst + 4) = v1;
    }
}

// ---------------- fused: attention step s  +  classifier for step s-1 ----------------
__global__ __launch_bounds__(128) void k_attn_cls(const float* __restrict__ x,
                                                  const float* __restrict__ v,
                                                  const float* __restrict__ b_cls,
                                                  float* __restrict__ out,
                                                  int cls_step, int n_attn) {
    int bid = blockIdx.x;
    int tid = threadIdx.x;

    if (bid < n_attn) {
        // ---- attention ----
        int chunk = bid & 15;
        int b = bid >> 4;
        int t0 = chunk * 128;

        __shared__ float q_s[An];
        __shared__ float v_s[An];
        __shared__ float w_s[128];
        __shared__ float red[4];

        q_s[tid] = g_q[b * An + tid];
        v_s[tid] = v[tid];
        __syncthreads();

        // phase A: e over A=128 (coalesced across t), unroll 8 for MLP
        const float* xw = g_xWT + (size_t)b * An * Tn + (t0 + tid);
        float e[8];
#pragma unroll
        for (int i = 0; i < 8; i++) e[i] = 0.f;
#pragma unroll 2
        for (int a = 0; a < An; a += 8) {
            float z[8], th[8];
#pragma unroll
            for (int i = 0; i < 8; i++) z[i] = xw[(size_t)(a + i) * Tn] + q_s[a + i];
#pragma unroll
            for (int i = 0; i < 8; i++)
                asm("tanh.approx.f32 %0, %1;" : "=f"(th[i]) : "f"(z[i]));
#pragma unroll
            for (int i = 0; i < 8; i++) e[i] += th[i] * v_s[a + i];
        }
        float ee = ((e[0] + e[1]) + (e[2] + e[3])) + ((e[4] + e[5]) + (e[6] + e[7]));
        // |e| <= sum|v| ~ 5 -> exp stable without max subtraction
        float w = __expf(ee);
        w_s[tid] = w;

        float s = w;
#pragma unroll
        for (int o = 16; o > 0; o >>= 1) s += __shfl_xor_sync(0xffffffffu, s, o);
        if ((tid & 31) == 0) red[tid >> 5] = s;
        __syncthreads();
        if (tid == 0) atomicAdd(&g_sumw[b], (red[0] + red[1]) + (red[2] + red[3]));

        // phase B: partial ctx; 128 threads cover 256 d via float2
        const float* xp = x + ((size_t)b * Tn + t0) * Dn + tid * 2;
        float ax = 0.f, ay = 0.f, bx = 0.f, by = 0.f;
#pragma unroll 2
        for (int t = 0; t < 128; t += 2) {
            float2 x0 = *(const float2*)(xp + (size_t)(t + 0) * Dn);
            float2 x1 = *(const float2*)(xp + (size_t)(t + 1) * Dn);
            ax += w_s[t + 0] * x0.x; ay += w_s[t + 0] * x0.y;
            bx += w_s[t + 1] * x1.x; by += w_s[t + 1] * x1.y;
        }
        atomicAdd(&g_ctx[b * Dn + tid * 2 + 0], ax + bx);
        atomicAdd(&g_ctx[b * Dn + tid * 2 + 1], ay + by);
    } else {
        // ---- classifier for step cls_step ----
        if (cls_step < 0) return;
        int cid = bid - n_attn;
        int ctile = cid % 35;
        int bg = cid / 35;
        int c = ctile * 128 + tid;
        int b0 = bg * 8;

        __shared__ float hs[8 * 256];
        for (int i = tid; i < 8 * 256; i += 128) hs[i] = g_h[b0 * Hn + i];
        __syncthreads();

        if (c < Cn) {
            float acc[8];
#pragma unroll
            for (int bb = 0; bb < 8; bb++) acc[bb] = 0.f;
#pragma unroll 4
            for (int k = 0; k < 256; k++) {
                float wv = g_WclsT[(size_t)k * CP + c];
#pragma unroll
                for (int bb = 0; bb < 8; bb++) acc[bb] += hs[bb * 256 + k] * wv;
            }
            float bias = b_cls[c];
#pragma unroll
            for (int bb = 0; bb < 8; bb++)
                out[((size_t)(b0 + bb) * NSTEPS + cls_step) * Cn + c] = acc[bb] + bias;
        }
    }
}

// ---------------- GRU gate GEMMs, split-k atomic version ----------------
// grid (6 j-tiles of 256, 32 b, 2 k-halves). jt<3 -> gi (ctx), jt>=3 -> gh (h).
// g_gi/g_gh pre-seeded with biases (k_init / previous k_update).
__global__ __launch_bounds__(256) void k_gates3() {
    int jt = blockIdx.x;
    int b  = blockIdx.y;
    int kh = blockIdx.z;
    int tid = threadIdx.x;
    int jg = jt * 256 + tid;           // 0..1535 (uniform gi/gh per block)
    bool is_gi = (jt < 3);
    int jj = is_gi ? jg : jg - 768;

    __shared__ float src[128];
    if (tid < 128) {
        int k = kh * 128 + tid;
        if (is_gi) {
            src[tid] = g_ctx[b * Dn + k] * (1.f / g_sumw[b]);
        } else {
            src[tid] = g_h[b * Hn + k];
        }
    }
    __syncthreads();

    const float* Wp = (is_gi ? g_WihT : g_WhhT) + (size_t)(kh * 128) * G3H + jj;
    float a0 = 0.f, a1 = 0.f, a2 = 0.f, a3 = 0.f;
#pragma unroll 8
    for (int k = 0; k < 128; k += 4) {
        a0 += src[k + 0] * Wp[(size_t)(k + 0) * G3H];
        a1 += src[k + 1] * Wp[(size_t)(k + 1) * G3H];
        a2 += src[k + 2] * Wp[(size_t)(k + 2) * G3H];
        a3 += src[k + 3] * Wp[(size_t)(k + 3) * G3H];
    }
    float* dst = is_gi ? g_gi : g_gh;
    atomicAdd(&dst[b * G3H + jj], (a0 + a1) + (a2 + a3));
}

// ---------------- GRU combine + h update + q = h@Wh + re-seed biases + zero scratch ----------------
__global__ __launch_bounds__(256) void k_update(const float* __restrict__ Wh,
                                                const float* __restrict__ b_ih,
                                                const float* __restrict__ b_hh) {
    int b = blockIdx.x;
    int tid = threadIdx.x;     // 256 = H
    __shared__ float hs[256];
    __shared__ float qp[128];

    float i_r = g_gi[b * G3H + tid];
    float i_z = g_gi[b * G3H + 256 + tid];
    float i_n = g_gi[b * G3H + 512 + tid];
    float h_r = g_gh[b * G3H + tid];
    float h_z = g_gh[b * G3H + 256 + tid];
    float h_n = g_gh[b * G3H + 512 + tid];
    float hprev = g_h[b * Hn + tid];

    float r = 1.f / (1.f + expf(-(i_r + h_r)));
    float z = 1.f / (1.f + expf(-(i_z + h_z)));
    float n = tanhf(i_n + r * h_n);
    float hn = (1.f - z) * n + z * hprev;

    g_h[b * Hn + tid] = hn;
    hs[tid] = hn;
    g_ctx[b * Dn + tid] = 0.f;                 // reset for next step
    if (tid == 0) g_sumw[b] = 0.f;
    // re-seed gate accumulators with biases for the NEXT step's k_gates3
    g_gi[b * G3H + tid]       = b_ih[tid];
    g_gi[b * G3H + 256 + tid] = b_ih[256 + tid];
    g_gi[b * G3H + 512 + tid] = b_ih[512 + tid];
    g_gh[b * G3H + tid]       = b_hh[tid];
    g_gh[b * G3H + 256 + tid] = b_hh[256 + tid];
    g_gh[b * G3H + 512 + tid] = b_hh[512 + tid];
    __syncthreads();

    // q[a] = sum_k hs[k] * Wh[k][a], split-k across the two thread halves
    int a = tid & 127;
    int half = tid >> 7;
    const float* Wp = Wh + (size_t)(half * 128) * An + a;
    float acc0 = 0.f, acc1 = 0.f;
#pragma unroll 8
    for (int k = 0; k < 128; k += 2) {
        acc0 += hs[half * 128 + k]     * Wp[(size_t)k * An];
        acc1 += hs[half * 128 + k + 1] * Wp[(size_t)(k + 1) * An];
    }
    if (half == 0) qp[a] = acc0 + acc1;
    __syncthreads();
    if (half == 1) g_q[b * An + a] = qp[a] + acc0 + acc1;
}

// ---------------- launch ----------------
extern "C" void kernel_launch(void* const* d_in, const int* in_sizes, int n_in,
                              void* d_out, int out_size) {
    const float* x     = (const float*)d_in[0];
    const float* Wx    = (const float*)d_in[1];
    const float* Wh    = (const float*)d_in[2];
    const float* v     = (const float*)d_in[3];
    const float* W_ih  = (const float*)d_in[4];
    const float* W_hh  = (const float*)d_in[5];
    const float* b_ih  = (const float*)d_in[6];
    const float* b_hh  = (const float*)d_in[7];
    const float* W_cls = (const float*)d_in[8];
    const float* b_cls = (const float*)d_in[9];
    float* out = (float*)d_out;

    k_init<<<1024, 256>>>(W_ih, W_hh, W_cls, b_ih, b_hh);
    k_xw<<<512, 256>>>(x, Wx);

    const int N_ATTN = 512;   // 16 t-chunks x 32 b
    const int N_CLS  = 140;   // 35 c-tiles x 4 b-groups

    for (int s = 0; s < NSTEPS; s++) {
        k_attn_cls<<<N_ATTN + N_CLS, 128>>>(x, v, b_cls, out, s - 1, N_ATTN);
        k_gates3<<<dim3(6, 32, 2), 256>>>();
        k_update<<<32, 256>>>(Wh, b_ih, b_hh);
    }
    // classifier for the final step
    k_attn_cls<<<N_CLS, 128>>>(x, v, b_cls, out, NSTEPS - 1, 0);

    (void)in_sizes; (void)n_in; (void)out_size;
}

// round 8
// speedup vs baseline: 1.6048x; 1.1652x over previous
#include <cuda_runtime.h>
#include <math.h>

#define Bn 32
#define Tn 2048
#define Dn 256
#define Hn 256
#define An 128
#define Cn 4367
#define CP 4368
#define NSTEPS 22
#define G3H 768

// ---------------- scratch (static device globals; no allocation) ----------------
__device__ float g_xWT[(size_t)Bn * An * Tn];   // [b][a][t]  ~33.5 MB
__device__ float g_h[Bn * Hn];
__device__ float g_q[Bn * An];
__device__ float g_ctx[Bn * Dn];                // unnormalized ctx accumulator
__device__ float g_sumw[Bn];
__device__ float g_gi[Bn * G3H];                // seeded with b_ih, atomically accumulated
__device__ float g_gh[Bn * G3H];                // seeded with b_hh, atomically accumulated
__device__ float g_WihT[Dn * G3H];              // [k][j]
__device__ float g_WhhT[Hn * G3H];              // [k][j]
__device__ float g_WclsT[Hn * CP];              // [k][c] padded to 4368
__device__ int   g_cnt[Bn];                     // ticket counters for fused update

// ---------------- init: transposes + zero state + bias-seed gates ----------------
__global__ void k_init(const float* __restrict__ W_ih,
                       const float* __restrict__ W_hh,
                       const float* __restrict__ W_cls,
                       const float* __restrict__ b_ih,
                       const float* __restrict__ b_hh) {
    int idx = blockIdx.x * blockDim.x + threadIdx.x;
    int stride = gridDim.x * blockDim.x;
    for (int i = idx; i < G3H * Dn; i += stride) {
        int j = i / Dn, k = i % Dn;
        g_WihT[k * G3H + j] = W_ih[i];
        g_WhhT[k * G3H + j] = W_hh[i];
    }
    for (int i = idx; i < Cn * Hn; i += stride) {
        int c = i / Hn, k = i % Hn;
        g_WclsT[k * CP + c] = W_cls[i];
    }
    for (int i = idx; i < Bn * Hn; i += stride) { g_h[i] = 0.f; g_ctx[i] = 0.f; }
    for (int i = idx; i < Bn * An; i += stride) g_q[i] = 0.f;
    for (int i = idx; i < Bn * G3H; i += stride) {
        g_gi[i] = b_ih[i % G3H];
        g_gh[i] = b_hh[i % G3H];
    }
    if (idx < Bn) { g_sumw[idx] = 0.f; g_cnt[idx] = 0; }
}

// ---------------- xW GEMM: [65536,256] @ [256,128] -> transposed [b][a][t] ----------------
// As stored K-MAJOR with 132-float row stride (16B-aligned rows) -> float4 LDS, broadcast reads.
__global__ __launch_bounds__(256) void k_xw(const float* __restrict__ x,
                                            const float* __restrict__ Wx) {
    __shared__ float As2[16][132];  // [k][t], row stride 132 floats = 528 B (16B aligned)
    __shared__ float Bs[16][128];   // [k][a]
    int rb = blockIdx.x;            // 512 blocks, 128 rows each (t-tiles never cross b)
    int row0 = rb * 128;
    int b = row0 / Tn;
    int t0 = row0 % Tn;
    int tid = threadIdx.x;
    int tt = tid / 16;              // t group (8 rows)
    int ta = tid % 16;              // a group (8 cols)

    float acc[8][8];
#pragma unroll
    for (int i = 0; i < 8; i++)
#pragma unroll
        for (int j = 0; j < 8; j++) acc[i][j] = 0.f;

    int lr = tid >> 1;              // t row this thread loads
    int lp = tid & 1;               // which 8-k half
    int lk = tid >> 5;              // Bs load: k row (0..7; also lk+8)
    int la = tid & 31;              // float4 col

    for (int k0 = 0; k0 < 256; k0 += 16) {
        const float* xs = x + (size_t)(row0 + lr) * Dn + k0 + lp * 8;
        float4 xa0 = *(const float4*)(xs);
        float4 xa1 = *(const float4*)(xs + 4);
        // scatter into k-major As2 (per fixed k, t=lr consecutive -> conflict-light)
        As2[lp * 8 + 0][lr] = xa0.x; As2[lp * 8 + 1][lr] = xa0.y;
        As2[lp * 8 + 2][lr] = xa0.z; As2[lp * 8 + 3][lr] = xa0.w;
        As2[lp * 8 + 4][lr] = xa1.x; As2[lp * 8 + 5][lr] = xa1.y;
        As2[lp * 8 + 6][lr] = xa1.z; As2[lp * 8 + 7][lr] = xa1.w;
        float4 w0 = *(const float4*)(Wx + (size_t)(k0 + lk) * An + la * 4);
        float4 w1 = *(const float4*)(Wx + (size_t)(k0 + lk + 8) * An + la * 4);
        *(float4*)(&Bs[lk][la * 4]) = w0;
        *(float4*)(&Bs[lk + 8][la * 4]) = w1;
        __syncthreads();
#pragma unroll
        for (int kk = 0; kk < 16; kk++) {
            float4 a0 = *(const float4*)(&As2[kk][tt * 8]);      // broadcast within warp
            float4 a1 = *(const float4*)(&As2[kk][tt * 8 + 4]);
            float4 b0 = *(const float4*)(&Bs[kk][ta * 8]);
            float4 b1 = *(const float4*)(&Bs[kk][ta * 8 + 4]);
            float af[8] = {a0.x, a0.y, a0.z, a0.w, a1.x, a1.y, a1.z, a1.w};
            float bf[8] = {b0.x, b0.y, b0.z, b0.w, b1.x, b1.y, b1.z, b1.w};
#pragma unroll
            for (int i = 0; i < 8; i++)
#pragma unroll
                for (int j = 0; j < 8; j++) acc[i][j] += af[i] * bf[j];
        }
        __syncthreads();
    }
#pragma unroll
    for (int j = 0; j < 8; j++) {
        int a = ta * 8 + j;
        float* dst = g_xWT + ((size_t)b * An + a) * Tn + t0 + tt * 8;
        float4 v0 = make_float4(acc[0][j], acc[1][j], acc[2][j], acc[3][j]);
        float4 v1 = make_float4(acc[4][j], acc[5][j], acc[6][j], acc[7][j]);
        *(float4*)dst = v0;
        *(float4*)(dst + 4) = v1;
    }
}

// ---------------- fused: attention step s  +  classifier for step s-1 ----------------
__global__ __launch_bounds__(128) void k_attn_cls(const float* __restrict__ x,
                                                  const float* __restrict__ v,
                                                  const float* __restrict__ b_cls,
                                                  float* __restrict__ out,
                                                  int cls_step, int n_attn) {
    int bid = blockIdx.x;
    int tid = threadIdx.x;

    if (bid < n_attn) {
        // ---- attention ----
        int chunk = bid & 15;
        int b = bid >> 4;
        int t0 = chunk * 128;

        __shared__ float q_s[An];
        __shared__ float v_s[An];
        __shared__ float w_s[128];
        __shared__ float red[4];

        q_s[tid] = g_q[b * An + tid];
        v_s[tid] = v[tid];
        __syncthreads();

        // phase A: e over A=128 (coalesced across t), unroll 8 for MLP
        const float* xw = g_xWT + (size_t)b * An * Tn + (t0 + tid);
        float e[8];
#pragma unroll
        for (int i = 0; i < 8; i++) e[i] = 0.f;
#pragma unroll 2
        for (int a = 0; a < An; a += 8) {
            float z[8], th[8];
#pragma unroll
            for (int i = 0; i < 8; i++) z[i] = xw[(size_t)(a + i) * Tn] + q_s[a + i];
#pragma unroll
            for (int i = 0; i < 8; i++)
                asm("tanh.approx.f32 %0, %1;" : "=f"(th[i]) : "f"(z[i]));
#pragma unroll
            for (int i = 0; i < 8; i++) e[i] += th[i] * v_s[a + i];
        }
        float ee = ((e[0] + e[1]) + (e[2] + e[3])) + ((e[4] + e[5]) + (e[6] + e[7]));
        // |e| <= sum|v| ~ 5 -> exp stable without max subtraction
        float w = __expf(ee);
        w_s[tid] = w;

        float s = w;
#pragma unroll
        for (int o = 16; o > 0; o >>= 1) s += __shfl_xor_sync(0xffffffffu, s, o);
        if ((tid & 31) == 0) red[tid >> 5] = s;
        __syncthreads();
        if (tid == 0) atomicAdd(&g_sumw[b], (red[0] + red[1]) + (red[2] + red[3]));

        // phase B: partial ctx; 128 threads cover 256 d via float2, t unroll 4
        const float* xp = x + ((size_t)b * Tn + t0) * Dn + tid * 2;
        float ax = 0.f, ay = 0.f, bx = 0.f, by = 0.f;
#pragma unroll 2
        for (int t = 0; t < 128; t += 4) {
            float2 x0 = *(const float2*)(xp + (size_t)(t + 0) * Dn);
            float2 x1 = *(const float2*)(xp + (size_t)(t + 1) * Dn);
            float2 x2 = *(const float2*)(xp + (size_t)(t + 2) * Dn);
            float2 x3 = *(const float2*)(xp + (size_t)(t + 3) * Dn);
            ax += w_s[t + 0] * x0.x; ay += w_s[t + 0] * x0.y;
            bx += w_s[t + 1] * x1.x; by += w_s[t + 1] * x1.y;
            ax += w_s[t + 2] * x2.x; ay += w_s[t + 2] * x2.y;
            bx += w_s[t + 3] * x3.x; by += w_s[t + 3] * x3.y;
        }
        atomicAdd(&g_ctx[b * Dn + tid * 2 + 0], ax + bx);
        atomicAdd(&g_ctx[b * Dn + tid * 2 + 1], ay + by);
    } else {
        // ---- classifier for step cls_step ----
        if (cls_step < 0) return;
        int cid = bid - n_attn;
        int ctile = cid % 35;
        int bg = cid / 35;
        int c = ctile * 128 + tid;
        int b0 = bg * 8;

        __shared__ float hs[8 * 256];
        for (int i = tid; i < 8 * 256; i += 128) hs[i] = g_h[b0 * Hn + i];
        __syncthreads();

        if (c < Cn) {
            float acc[8];
#pragma unroll
            for (int bb = 0; bb < 8; bb++) acc[bb] = 0.f;
#pragma unroll 4
            for (int k = 0; k < 256; k++) {
                float wv = g_WclsT[(size_t)k * CP + c];
#pragma unroll
                for (int bb = 0; bb < 8; bb++) acc[bb] += hs[bb * 256 + k] * wv;
            }
            float bias = b_cls[c];
#pragma unroll
            for (int bb = 0; bb < 8; bb++)
                out[((size_t)(b0 + bb) * NSTEPS + cls_step) * Cn + c] = acc[bb] + bias;
        }
    }
}

// ---------------- GRU gates (split-k=4, atomic) + ticket-fused GRU update ----------------
// grid (6 j-tiles, 32 b, 4 k-quarters) = 768 blocks. jt<3 -> gi (ctx/sumw), jt>=3 -> gh (h).
// The LAST block to finish for a given b (ticket==23) runs the full GRU update inline.
__global__ __launch_bounds__(256) void k_gates4(const float* __restrict__ Wh,
                                                const float* __restrict__ b_ih,
                                                const float* __restrict__ b_hh) {
    int jt = blockIdx.x;
    int b  = blockIdx.y;
    int kq = blockIdx.z;               // 0..3, k-chunk 64
    int tid = threadIdx.x;
    int jg = jt * 256 + tid;           // 0..1535 (uniform gi/gh per block)
    bool is_gi = (jt < 3);
    int jj = is_gi ? jg : jg - 768;

    __shared__ float src[64];
    __shared__ int ticket_s;
    if (tid < 64) {
        int k = kq * 64 + tid;
        src[tid] = is_gi ? (g_ctx[b * Dn + k] * (1.f / g_sumw[b]))
                         : g_h[b * Hn + k];
    }
    __syncthreads();

    const float* Wp = (is_gi ? g_WihT : g_WhhT) + (size_t)(kq * 64) * G3H + jj;
    float a0 = 0.f, a1 = 0.f, a2 = 0.f, a3 = 0.f;
#pragma unroll 4
    for (int k = 0; k < 64; k += 4) {
        a0 += src[k + 0] * Wp[(size_t)(k + 0) * G3H];
        a1 += src[k + 1] * Wp[(size_t)(k + 1) * G3H];
        a2 += src[k + 2] * Wp[(size_t)(k + 2) * G3H];
        a3 += src[k + 3] * Wp[(size_t)(k + 3) * G3H];
    }
    float* dst = is_gi ? g_gi : g_gh;
    atomicAdd(&dst[b * G3H + jj], (a0 + a1) + (a2 + a3));

    // ---- ticket: last of the 24 blocks for this b runs the GRU update ----
    __threadfence();
    if (tid == 0) ticket_s = atomicAdd(&g_cnt[b], 1);
    __syncthreads();
    if (ticket_s != 23) return;
    __threadfence();                   // acquire all other blocks' gi/gh writes

    __shared__ float hs[256];
    __shared__ float qp[128];

    float i_r = g_gi[b * G3H + tid];
    float i_z = g_gi[b * G3H + 256 + tid];
    float i_n = g_gi[b * G3H + 512 + tid];
    float h_r = g_gh[b * G3H + tid];
    float h_z = g_gh[b * G3H + 256 + tid];
    float h_n = g_gh[b * G3H + 512 + tid];
    float hprev = g_h[b * Hn + tid];

    float r = 1.f / (1.f + expf(-(i_r + h_r)));
    float z = 1.f / (1.f + expf(-(i_z + h_z)));
    float n = tanhf(i_n + r * h_n);
    float hn = (1.f - z) * n + z * hprev;

    g_h[b * Hn + tid] = hn;
    hs[tid] = hn;
    g_ctx[b * Dn + tid] = 0.f;                 // reset for next step
    if (tid == 0) { g_sumw[b] = 0.f; g_cnt[b] = 0; }
    // re-seed gate accumulators with biases for the NEXT step
    g_gi[b * G3H + tid]       = b_ih[tid];
    g_gi[b * G3H + 256 + tid] = b_ih[256 + tid];
    g_gi[b * G3H + 512 + tid] = b_ih[512 + tid];
    g_gh[b * G3H + tid]       = b_hh[tid];
    g_gh[b * G3H + 256 + tid] = b_hh[256 + tid];
    g_gh[b * G3H + 512 + tid] = b_hh[512 + tid];
    __syncthreads();

    // q[a] = sum_k hs[k] * Wh[k][a], split-k across the two thread halves
    int a = tid & 127;
    int half = tid >> 7;
    const float* Wq = Wh + (size_t)(half * 128) * An + a;
    float acc0 = 0.f, acc1 = 0.f;
#pragma unroll 8
    for (int k = 0; k < 128; k += 2) {
        acc0 += hs[half * 128 + k]     * Wq[(size_t)k * An];
        acc1 += hs[half * 128 + k + 1] * Wq[(size_t)(k + 1) * An];
    }
    if (half == 0) qp[a] = acc0 + acc1;
    __syncthreads();
    if (half == 1) g_q[b * An + a] = qp[a] + acc0 + acc1;
}

// ---------------- launch ----------------
extern "C" void kernel_launch(void* const* d_in, const int* in_sizes, int n_in,
                              void* d_out, int out_size) {
    const float* x     = (const float*)d_in[0];
    const float* Wx    = (const float*)d_in[1];
    const float* Wh    = (const float*)d_in[2];
    const float* v     = (const float*)d_in[3];
    const float* W_ih  = (const float*)d_in[4];
    const float* W_hh  = (const float*)d_in[5];
    const float* b_ih  = (const float*)d_in[6];
    const float* b_hh  = (const float*)d_in[7];
    const float* W_cls = (const float*)d_in[8];
    const float* b_cls = (const float*)d_in[9];
    float* out = (float*)d_out;

    k_init<<<1024, 256>>>(W_ih, W_hh, W_cls, b_ih, b_hh);
    k_xw<<<512, 256>>>(x, Wx);

    const int N_ATTN = 512;   // 16 t-chunks x 32 b
    const int N_CLS  = 140;   // 35 c-tiles x 4 b-groups

    for (int s = 0; s < NSTEPS; s++) {
        k_attn_cls<<<N_ATTN + N_CLS, 128>>>(x, v, b_cls, out, s - 1, N_ATTN);
        k_gates4<<<dim3(6, 32, 4), 256>>>(Wh, b_ih, b_hh);
    }
    // classifier for the final step
    k_attn_cls<<<N_CLS, 128>>>(x, v, b_cls, out, NSTEPS - 1, 0);

    (void)in_sizes; (void)n_in; (void)out_size;
}

// round 9
// speedup vs baseline: 2.6845x; 1.6728x over previous
#include <cuda_runtime.h>
#include <cuda_bf16.h>
#include <math.h>

#define Bn 32
#define Tn 2048
#define Dn 256
#define Hn 256
#define An 128
#define Cn 4367
#define CP 4368
#define NSTEPS 22
#define G3H 768

// ---------------- scratch (static device globals; no allocation) ----------------
__device__ __nv_bfloat16 g_xWTb[(size_t)Bn * An * Tn];  // [b][a][t] bf16 ~16.8 MB
__device__ float g_h[Bn * Hn];
__device__ float g_q[Bn * An];
__device__ float g_ctx[Bn * Dn];                // unnormalized ctx accumulator
__device__ float g_sumw[Bn];
__device__ float g_gi[Bn * G3H];                // seeded with b_ih, atomically accumulated
__device__ float g_gh[Bn * G3H];                // seeded with b_hh, atomically accumulated
__device__ float g_WihT[Dn * G3H];              // [k][j]
__device__ float g_WhhT[Hn * G3H];              // [k][j]
__device__ float g_WclsT[Hn * CP];              // [k][c] padded to 4368

// ---------------- init: transposes + zero state + bias-seed gates ----------------
__global__ void k_init(const float* __restrict__ W_ih,
                       const float* __restrict__ W_hh,
                       const float* __restrict__ W_cls,
                       const float* __restrict__ b_ih,
                       const float* __restrict__ b_hh) {
    int idx = blockIdx.x * blockDim.x + threadIdx.x;
    int stride = gridDim.x * blockDim.x;
    for (int i = idx; i < G3H * Dn; i += stride) {
        int j = i / Dn, k = i % Dn;
        g_WihT[k * G3H + j] = W_ih[i];
        g_WhhT[k * G3H + j] = W_hh[i];
    }
    for (int i = idx; i < Cn * Hn; i += stride) {
        int c = i / Hn, k = i % Hn;
        g_WclsT[k * CP + c] = W_cls[i];
    }
    for (int i = idx; i < Bn * Hn; i += stride) { g_h[i] = 0.f; g_ctx[i] = 0.f; }
    for (int i = idx; i < Bn * An; i += stride) g_q[i] = 0.f;
    for (int i = idx; i < Bn * G3H; i += stride) {
        g_gi[i] = b_ih[i % G3H];
        g_gh[i] = b_hh[i % G3H];
    }
    if (idx < Bn) g_sumw[idx] = 0.f;
}

// nop for ncu launch alignment (-s 5 -c 1 profiles launch #6)
__global__ void k_nop() {}

// ---------------- xW GEMM: [65536,256] @ [256,128] -> bf16 transposed [b][a][t] ----------------
__global__ __launch_bounds__(256) void k_xw(const float* __restrict__ x,
                                            const float* __restrict__ Wx) {
    __shared__ float As2[16][132];  // [k][t], row stride 132 floats (16B-aligned rows)
    __shared__ float Bs[16][128];   // [k][a]
    int rb = blockIdx.x;            // 512 blocks, 128 rows each (t-tiles never cross b)
    int row0 = rb * 128;
    int b = row0 / Tn;
    int t0 = row0 % Tn;
    int tid = threadIdx.x;
    int tt = tid / 16;              // t group (8 rows)
    int ta = tid % 16;              // a group (8 cols)

    float acc[8][8];
#pragma unroll
    for (int i = 0; i < 8; i++)
#pragma unroll
        for (int j = 0; j < 8; j++) acc[i][j] = 0.f;

    int lr = tid >> 1;              // t row this thread loads
    int lp = tid & 1;               // which 8-k half
    int lk = tid >> 5;              // Bs load: k row (0..7; also lk+8)
    int la = tid & 31;              // float4 col

    for (int k0 = 0; k0 < 256; k0 += 16) {
        const float* xs = x + (size_t)(row0 + lr) * Dn + k0 + lp * 8;
        float4 xa0 = *(const float4*)(xs);
        float4 xa1 = *(const float4*)(xs + 4);
        As2[lp * 8 + 0][lr] = xa0.x; As2[lp * 8 + 1][lr] = xa0.y;
        As2[lp * 8 + 2][lr] = xa0.z; As2[lp * 8 + 3][lr] = xa0.w;
        As2[lp * 8 + 4][lr] = xa1.x; As2[lp * 8 + 5][lr] = xa1.y;
        As2[lp * 8 + 6][lr] = xa1.z; As2[lp * 8 + 7][lr] = xa1.w;
        float4 w0 = *(const float4*)(Wx + (size_t)(k0 + lk) * An + la * 4);
        float4 w1 = *(const float4*)(Wx + (size_t)(k0 + lk + 8) * An + la * 4);
        *(float4*)(&Bs[lk][la * 4]) = w0;
        *(float4*)(&Bs[lk + 8][la * 4]) = w1;
        __syncthreads();
#pragma unroll
        for (int kk = 0; kk < 16; kk++) {
            float4 a0 = *(const float4*)(&As2[kk][tt * 8]);
            float4 a1 = *(const float4*)(&As2[kk][tt * 8 + 4]);
            float4 b0 = *(const float4*)(&Bs[kk][ta * 8]);
            float4 b1 = *(const float4*)(&Bs[kk][ta * 8 + 4]);
            float af[8] = {a0.x, a0.y, a0.z, a0.w, a1.x, a1.y, a1.z, a1.w};
            float bf[8] = {b0.x, b0.y, b0.z, b0.w, b1.x, b1.y, b1.z, b1.w};
#pragma unroll
            for (int i = 0; i < 8; i++)
#pragma unroll
                for (int j = 0; j < 8; j++) acc[i][j] += af[i] * bf[j];
        }
        __syncthreads();
    }
    // write bf16 transposed: 8 consecutive t per thread = 16 bytes (aligned: t0+tt*8 % 8 == 0)
#pragma unroll
    for (int j = 0; j < 8; j++) {
        int a = ta * 8 + j;
        __nv_bfloat16* dst = g_xWTb + ((size_t)b * An + a) * Tn + t0 + tt * 8;
        __nv_bfloat162 p[4];
        p[0] = __floats2bfloat162_rn(acc[0][j], acc[1][j]);
        p[1] = __floats2bfloat162_rn(acc[2][j], acc[3][j]);
        p[2] = __floats2bfloat162_rn(acc[4][j], acc[5][j]);
        p[3] = __floats2bfloat162_rn(acc[6][j], acc[7][j]);
        *(uint4*)dst = *(uint4*)p;
    }
}

// ---------------- fused: attention step s  +  classifier for step s-1 ----------------
__global__ __launch_bounds__(128) void k_attn_cls(const float* __restrict__ x,
                                                  const float* __restrict__ v,
                                                  const float* __restrict__ b_cls,
                                                  float* __restrict__ out,
                                                  int cls_step, int n_attn) {
    int bid = blockIdx.x;
    int tid = threadIdx.x;

    if (bid < n_attn) {
        // ---- attention ----
        int chunk = bid & 15;
        int b = bid >> 4;
        int t0 = chunk * 128;

        __shared__ float q_s[An];
        __shared__ float v_s[An];
        __shared__ float w_s[128];
        __shared__ float red[4];

        q_s[tid] = g_q[b * An + tid];
        v_s[tid] = v[tid];
        __syncthreads();

        // phase A: e over A=128 (bf16 xWT, coalesced across t), unroll 8 for MLP
        const __nv_bfloat16* xw = g_xWTb + (size_t)b * An * Tn + (t0 + tid);
        float e[8];
#pragma unroll
        for (int i = 0; i < 8; i++) e[i] = 0.f;
#pragma unroll 2
        for (int a = 0; a < An; a += 8) {
            float z[8], th[8];
#pragma unroll
            for (int i = 0; i < 8; i++)
                z[i] = __bfloat162float(xw[(size_t)(a + i) * Tn]) + q_s[a + i];
#pragma unroll
            for (int i = 0; i < 8; i++)
                asm("tanh.approx.f32 %0, %1;" : "=f"(th[i]) : "f"(z[i]));
#pragma unroll
            for (int i = 0; i < 8; i++) e[i] += th[i] * v_s[a + i];
        }
        float ee = ((e[0] + e[1]) + (e[2] + e[3])) + ((e[4] + e[5]) + (e[6] + e[7]));
        // |e| <= sum|v| ~ 5 -> exp stable without max subtraction
        float w = __expf(ee);
        w_s[tid] = w;

        float s = w;
#pragma unroll
        for (int o = 16; o > 0; o >>= 1) s += __shfl_xor_sync(0xffffffffu, s, o);
        if ((tid & 31) == 0) red[tid >> 5] = s;
        __syncthreads();
        if (tid == 0) atomicAdd(&g_sumw[b], (red[0] + red[1]) + (red[2] + red[3]));

        // phase B: partial ctx; 128 threads cover 256 d via float2, t unroll 4
        const float* xp = x + ((size_t)b * Tn + t0) * Dn + tid * 2;
        float ax = 0.f, ay = 0.f, bx = 0.f, by = 0.f;
#pragma unroll 2
        for (int t = 0; t < 128; t += 4) {
            float2 x0 = *(const float2*)(xp + (size_t)(t + 0) * Dn);
            float2 x1 = *(const float2*)(xp + (size_t)(t + 1) * Dn);
            float2 x2 = *(const float2*)(xp + (size_t)(t + 2) * Dn);
            float2 x3 = *(const float2*)(xp + (size_t)(t + 3) * Dn);
            ax += w_s[t + 0] * x0.x; ay += w_s[t + 0] * x0.y;
            bx += w_s[t + 1] * x1.x; by += w_s[t + 1] * x1.y;
            ax += w_s[t + 2] * x2.x; ay += w_s[t + 2] * x2.y;
            bx += w_s[t + 3] * x3.x; by += w_s[t + 3] * x3.y;
        }
        atomicAdd(&g_ctx[b * Dn + tid * 2 + 0], ax + bx);
        atomicAdd(&g_ctx[b * Dn + tid * 2 + 1], ay + by);
    } else {
        // ---- classifier for step cls_step ----
        if (cls_step < 0) return;
        int cid = bid - n_attn;
        int ctile = cid % 35;
        int bg = cid / 35;
        int c = ctile * 128 + tid;
        int b0 = bg * 8;

        __shared__ float hs[8 * 256];
        for (int i = tid; i < 8 * 256; i += 128) hs[i] = g_h[b0 * Hn + i];
        __syncthreads();

        if (c < Cn) {
            float acc[8];
#pragma unroll
            for (int bb = 0; bb < 8; bb++) acc[bb] = 0.f;
#pragma unroll 4
            for (int k = 0; k < 256; k++) {
                float wv = g_WclsT[(size_t)k * CP + c];
#pragma unroll
                for (int bb = 0; bb < 8; bb++) acc[bb] += hs[bb * 256 + k] * wv;
            }
            float bias = b_cls[c];
#pragma unroll
            for (int bb = 0; bb < 8; bb++)
                out[((size_t)(b0 + bb) * NSTEPS + cls_step) * Cn + c] = acc[bb] + bias;
        }
    }
}

// ---------------- GRU gates, b-tiled: each weight element loaded ONCE per step ----------------
// grid (24 j-tiles of 64, 8 k-chunks of 32) = 192 blocks x 256 thr.
// jt<12 -> gi (ctx/sumw), jt>=12 -> gh (h). thread = 1 j x 8 b.
// smem src[kk][b] -> warp reads are pure broadcast; W loads coalesced across j.
__global__ __launch_bounds__(256) void k_gates5() {
    int jt = blockIdx.x;               // 0..23
    int kq = blockIdx.y;               // 0..7
    int tid = threadIdx.x;
    bool is_gi = (jt < 12);
    int jj = (is_gi ? jt : jt - 12) * 64 + (tid & 63);
    int bg = tid >> 6;                 // 0..3 -> 8 b each
    int k0 = kq * 32;

    __shared__ float invw[Bn];
    __shared__ float src[32][32];      // [kk][b]

    if (tid < Bn) invw[tid] = 1.f / g_sumw[tid];
    __syncthreads();
    for (int i = tid; i < 32 * 32; i += 256) {
        int kk = i >> 5, b = i & 31;
        src[kk][b] = is_gi ? (g_ctx[b * Dn + k0 + kk] * invw[b])
                           : g_h[b * Hn + k0 + kk];
    }
    __syncthreads();

    const float* Wp = (is_gi ? g_WihT : g_WhhT) + (size_t)k0 * G3H + jj;
    float acc[8];
#pragma unroll
    for (int bb = 0; bb < 8; bb++) acc[bb] = 0.f;
#pragma unroll 8
    for (int kk = 0; kk < 32; kk++) {
        float w = Wp[(size_t)kk * G3H];
        const float* sp = &src[kk][bg * 8];
#pragma unroll
        for (int bb = 0; bb < 8; bb++) acc[bb] += sp[bb] * w;
    }
    float* dst = is_gi ? g_gi : g_gh;
#pragma unroll
    for (int bb = 0; bb < 8; bb++)
        atomicAdd(&dst[(bg * 8 + bb) * G3H + jj], acc[bb]);
}

// ---------------- GRU combine + h update + q = h@Wh + re-seed biases + zero scratch ----------------
__global__ __launch_bounds__(256) void k_update(const float* __restrict__ Wh,
                                                const float* __restrict__ b_ih,
                                                const float* __restrict__ b_hh) {
    int b = blockIdx.x;
    int tid = threadIdx.x;     // 256 = H
    __shared__ float hs[256];
    __shared__ float qp[128];

    float i_r = g_gi[b * G3H + tid];
    float i_z = g_gi[b * G3H + 256 + tid];
    float i_n = g_gi[b * G3H + 512 + tid];
    float h_r = g_gh[b * G3H + tid];
    float h_z = g_gh[b * G3H + 256 + tid];
    float h_n = g_gh[b * G3H + 512 + tid];
    float hprev = g_h[b * Hn + tid];

    float r = 1.f / (1.f + expf(-(i_r + h_r)));
    float z = 1.f / (1.f + expf(-(i_z + h_z)));
    float n = tanhf(i_n + r * h_n);
    float hn = (1.f - z) * n + z * hprev;

    g_h[b * Hn + tid] = hn;
    hs[tid] = hn;
    g_ctx[b * Dn + tid] = 0.f;                 // reset for next step
    if (tid == 0) g_sumw[b] = 0.f;
    // re-seed gate accumulators with biases for the NEXT step
    g_gi[b * G3H + tid]       = b_ih[tid];
    g_gi[b * G3H + 256 + tid] = b_ih[256 + tid];
    g_gi[b * G3H + 512 + tid] = b_ih[512 + tid];
    g_gh[b * G3H + tid]       = b_hh[tid];
    g_gh[b * G3H + 256 + tid] = b_hh[256 + tid];
    g_gh[b * G3H + 512 + tid] = b_hh[512 + tid];
    __syncthreads();

    // q[a] = sum_k hs[k] * Wh[k][a], split-k across the two thread halves
    int a = tid & 127;
    int half = tid >> 7;
    const float* Wq = Wh + (size_t)(half * 128) * An + a;
    float acc0 = 0.f, acc1 = 0.f;
#pragma unroll 8
    for (int k = 0; k < 128; k += 2) {
        acc0 += hs[half * 128 + k]     * Wq[(size_t)k * An];
        acc1 += hs[half * 128 + k + 1] * Wq[(size_t)(k + 1) * An];
    }
    if (half == 0) qp[a] = acc0 + acc1;
    __syncthreads();
    if (half == 1) g_q[b * An + a] = qp[a] + acc0 + acc1;
}

// ---------------- launch ----------------
extern "C" void kernel_launch(void* const* d_in, const int* in_sizes, int n_in,
                              void* d_out, int out_size) {
    const float* x     = (const float*)d_in[0];
    const float* Wx    = (const float*)d_in[1];
    const float* Wh    = (const float*)d_in[2];
    const float* v     = (const float*)d_in[3];
    const float* W_ih  = (const float*)d_in[4];
    const float* W_hh  = (const float*)d_in[5];
    const float* b_ih  = (const float*)d_in[6];
    const float* b_hh  = (const float*)d_in[7];
    const float* W_cls = (const float*)d_in[8];
    const float* b_cls = (const float*)d_in[9];
    float* out = (float*)d_out;

    k_init<<<1024, 256>>>(W_ih, W_hh, W_cls, b_ih, b_hh);
    k_xw<<<512, 256>>>(x, Wx);
    // 3 nops so ncu's skip-5 capture lands on the first k_attn_cls
    k_nop<<<1, 32>>>();
    k_nop<<<1, 32>>>();
    k_nop<<<1, 32>>>();

    const int N_ATTN = 512;   // 16 t-chunks x 32 b
    const int N_CLS  = 140;   // 35 c-tiles x 4 b-groups

    for (int s = 0; s < NSTEPS; s++) {
        k_attn_cls<<<N_ATTN + N_CLS, 128>>>(x, v, b_cls, out, s - 1, N_ATTN);
        k_gates5<<<dim3(24, 8), 256>>>();
        k_update<<<32, 256>>>(Wh, b_ih, b_hh);
    }
    // classifier for the final step
    k_attn_cls<<<N_CLS, 128>>>(x, v, b_cls, out, NSTEPS - 1, 0);

    (void)in_sizes; (void)n_in; (void)out_size;
}